// round 2
// baseline (speedup 1.0000x reference)
#include <cuda_runtime.h>

#define BATCH 4096
#define SEQT  256
#define DIN   32
#define HID   64
#define GATES 256
#define BT    32
#define NTHR  512
#define NCTA  128
#define WST   512          // floats per k2 row of weights (256 n * 2)
#define MST   64           // floats per k2 row of activations (32 m * 2)

typedef unsigned long long u64;

// ---- global scratch: k-pair interleaved weight layouts, built by prep ----
__device__ __align__(16) float g_W0p[32 * WST];    // Whh0  [k2][n][k-parity]
__device__ __align__(16) float g_Wx0p[16 * WST];   // Wih0  (read from L2 each step)
__device__ __align__(16) float g_W1p[64 * WST];    // [Wih1; Whh1]
__device__ __align__(16) float g_B0p[2 * GATES];   // packed {bias, 0}
__device__ __align__(16) float g_B1p[2 * GATES];

__global__ void prep_kernel(const float* __restrict__ Wih0, const float* __restrict__ Whh0,
                            const float* __restrict__ bih0, const float* __restrict__ bhh0,
                            const float* __restrict__ Wih1, const float* __restrict__ Whh1,
                            const float* __restrict__ bih1, const float* __restrict__ bhh1)
{
    int i = blockIdx.x * blockDim.x + threadIdx.x;
    int stride = gridDim.x * blockDim.x;
    for (int j = i; j < 32 * WST; j += stride) {
        int k2 = j / WST, r = j % WST, n = r >> 1, kk = r & 1;
        g_W0p[j] = Whh0[n * HID + 2 * k2 + kk];
    }
    for (int j = i; j < 16 * WST; j += stride) {
        int k2 = j / WST, r = j % WST, n = r >> 1, kk = r & 1;
        g_Wx0p[j] = Wih0[n * DIN + 2 * k2 + kk];
    }
    for (int j = i; j < 64 * WST; j += stride) {
        int k2 = j / WST, r = j % WST, n = r >> 1, kk = r & 1;
        int k = 2 * k2 + kk;
        g_W1p[j] = (k < HID) ? Wih1[n * HID + k] : Whh1[n * HID + (k - HID)];
    }
    for (int j = i; j < GATES; j += stride) {
        g_B0p[2 * j] = bih0[j] + bhh0[j]; g_B0p[2 * j + 1] = 0.0f;
        g_B1p[2 * j] = bih1[j] + bhh1[j]; g_B1p[2 * j + 1] = 0.0f;
    }
}

// ---- packed f32x2 helpers ----
__device__ __forceinline__ u64 fma2(u64 a, u64 b, u64 c) {
    u64 d;
    asm("fma.rn.f32x2 %0, %1, %2, %3;" : "=l"(d) : "l"(a), "l"(b), "l"(c));
    return d;
}
__device__ __forceinline__ float2 unpack2(u64 v) {
    float2 f;
    asm("mov.b64 {%0, %1}, %2;" : "=f"(f.x), "=f"(f.y) : "l"(v));
    return f;
}

// ---- fast activations (MUFU EX2/RCP, ~1e-7 rel err; proven 2.6e-7 end-to-end) ----
__device__ __forceinline__ float fast_ex2(float x) {
    float y; asm("ex2.approx.f32 %0, %1;" : "=f"(y) : "f"(x)); return y;
}
__device__ __forceinline__ float fast_rcp(float x) {
    float y; asm("rcp.approx.f32 %0, %1;" : "=f"(y) : "f"(x)); return y;
}
__device__ __forceinline__ float sigf(float x) {
    return fast_rcp(1.0f + fast_ex2(-1.4426950408889634f * x));
}
__device__ __forceinline__ float tanhf_fast(float x) {
    x = fminf(fmaxf(x, -15.0f), 15.0f);
    float e = fast_ex2(-2.8853900817779268f * x);  // exp(-2x)
    return (1.0f - e) * fast_rcp(1.0f + e);
}

// acc[m][g][j]: m in {0,1} batch rows, g gate, j u-column pair-member.
// Each acc lane pair holds (even-k partial + bias, odd-k partial).
template <int K2N>
__device__ __forceinline__ void gemm_block(const float* __restrict__ aT,
                                           const float* __restrict__ W,
                                           int m4, int u2, u64 acc[2][4][2])
{
#pragma unroll 2
    for (int k2 = 0; k2 < K2N; k2++) {
        ulonglong2 ha = *(const ulonglong2*)(aT + k2 * MST + m4);
#pragma unroll
        for (int g = 0; g < 4; g++) {
            ulonglong2 w = *(const ulonglong2*)(W + k2 * WST + g * 128 + u2);
            acc[0][g][0] = fma2(ha.x, w.x, acc[0][g][0]);
            acc[0][g][1] = fma2(ha.x, w.y, acc[0][g][1]);
            acc[1][g][0] = fma2(ha.y, w.x, acc[1][g][0]);
            acc[1][g][1] = fma2(ha.y, w.y, acc[1][g][1]);
        }
    }
}

__device__ __forceinline__ void acc_init(const float* __restrict__ sB, int u2, u64 acc[2][4][2])
{
#pragma unroll
    for (int g = 0; g < 4; g++) {
        ulonglong2 b = *(const ulonglong2*)(sB + g * 128 + u2);
        acc[0][g][0] = b.x; acc[0][g][1] = b.y;
        acc[1][g][0] = b.x; acc[1][g][1] = b.y;
    }
}

__device__ __forceinline__ void lstm_update(u64 acc[2][4][2], float c[2][2],
                                            float* __restrict__ hT, int gq, int m4)
{
    float h[2][2];
#pragma unroll
    for (int m = 0; m < 2; m++) {
#pragma unroll
        for (int j = 0; j < 2; j++) {
            float2 pi = unpack2(acc[m][0][j]);
            float2 pf = unpack2(acc[m][1][j]);
            float2 pg = unpack2(acc[m][2][j]);
            float2 po = unpack2(acc[m][3][j]);
            float iv = sigf(pi.x + pi.y);
            float fv = sigf(pf.x + pf.y);
            float gv = tanhf_fast(pg.x + pg.y);
            float ov = sigf(po.x + po.y);
            float cc = fv * c[m][j] + iv * gv;
            c[m][j] = cc;
            h[m][j] = ov * tanhf_fast(cc);
        }
    }
    *(float4*)(hT + gq * MST + m4) = make_float4(h[0][0], h[0][1], h[1][0], h[1][1]);
}

// Shared layout (floats)
#define OFF_W0 0
#define OFF_W1 (OFF_W0 + 32 * WST)     // 16384
#define OFF_B0 (OFF_W1 + 64 * WST)     // 49152
#define OFF_B1 (OFF_B0 + 2 * GATES)    // 49664
#define OFF_H0 (OFF_B1 + 2 * GATES)    // 50176
#define OFF_H1 (OFF_H0 + 32 * MST)     // 52224
#define OFF_X  (OFF_H1 + 32 * MST)     // 54272
#define SMEMF  (OFF_X + 16 * MST)      // 55296 floats = 221184 B

__global__ void __launch_bounds__(NTHR, 1)
lstm_fused(const float* __restrict__ x,
           const float* __restrict__ W1h, const float* __restrict__ b1h,
           const float* __restrict__ W2h, const float* __restrict__ b2h,
           float* __restrict__ out)
{
    extern __shared__ float sm[];
    float* sW0 = sm + OFF_W0;
    float* sW1 = sm + OFF_W1;
    float* sB0 = sm + OFF_B0;
    float* sB1 = sm + OFF_B1;
    float* h0T = sm + OFF_H0;
    float* h1T = sm + OFF_H1;
    float* xT  = sm + OFF_X;

    const int tid = threadIdx.x;
    const int b0  = blockIdx.x * BT;

    // stage weights + zero states
    {
        const float4* s0 = (const float4*)g_W0p;
        float4* d0 = (float4*)sW0;
        for (int i = tid; i < 32 * WST / 4; i += NTHR) d0[i] = s0[i];
        const float4* s1 = (const float4*)g_W1p;
        float4* d1 = (float4*)sW1;
        for (int i = tid; i < 64 * WST / 4; i += NTHR) d1[i] = s1[i];
        if (tid < 128)      ((float4*)sB0)[tid]       = ((const float4*)g_B0p)[tid];
        else if (tid < 256) ((float4*)sB1)[tid - 128] = ((const float4*)g_B1p)[tid - 128];
        for (int i = tid; i < 64 * MST; i += NTHR) h0T[i] = 0.0f;  // h0T + h1T contiguous
    }

    const int gm = tid & 15;       // 16 m-groups (2 rows each)
    const int gq = tid >> 4;       // 32 u-pair groups
    const int m4 = gm * 4;         // float offset of m0 in a k2-row
    const int u2 = gq * 4;         // float offset of n=u0 within a gate block

    // x staging: row xm, float2 chunk xd
    const int xm = tid >> 4;
    const int xd = tid & 15;
    const float* xrow = x + (size_t)(b0 + xm) * SEQT * DIN + xd * 2;

    float2 xv = *(const float2*)(xrow);              // x(0)
    *(float2*)(xT + xd * MST + xm * 2) = xv;         // stage t=0
    xv = *(const float2*)(xrow + DIN);               // prefetch x(1)
    __syncthreads();

    float c0[2][2] = {{0.f, 0.f}, {0.f, 0.f}};
    float c1[2][2] = {{0.f, 0.f}, {0.f, 0.f}};
    u64 acc[2][4][2];

    // gemm0(t=0)
    acc_init(sB0, u2, acc);
    gemm_block<32>(h0T, sW0, m4, u2, acc);
    gemm_block<16>(xT, g_Wx0p, m4, u2, acc);

    for (int t = 0; t < SEQT; t++) {
        __syncthreads();                             // B1: gemm0(t) done everywhere
        lstm_update(acc, c0, h0T, gq, m4);           // update layer 0
        *(float2*)(xT + xd * MST + xm * 2) = xv;     // stage x(t+1)
        int tn = (t + 2 < SEQT) ? t + 2 : SEQT - 1;
        xv = *(const float2*)(xrow + (size_t)tn * DIN);
        __syncthreads();                             // B2: h0T new + xT staged
        acc_init(sB1, u2, acc);
        gemm_block<32>(h0T, sW1, m4, u2, acc);       // Wih1 * h0(t)
        gemm_block<32>(h1T, sW1 + 32 * WST, m4, u2, acc); // Whh1 * h1(t-1)
        __syncthreads();                             // B3: gemm1 readers done
        lstm_update(acc, c1, h1T, gq, m4);           // update layer 1
        if (t + 1 < SEQT) {                          // overlap: gemm0(t+1)
            acc_init(sB0, u2, acc);
            gemm_block<32>(h0T, sW0, m4, u2, acc);
            gemm_block<16>(xT, g_Wx0p, m4, u2, acc);
        }
    }
    __syncthreads();

    // ---- head: out[m] = b2 + sum_n W2[n] * relu(b1[n] + sum_k h1(k,m) W1[n,k]) ----
    {
        int m = tid >> 4;      // 0..31
        int q = tid & 15;      // 0..15
        float pm = 0.0f;
#pragma unroll
        for (int jj = 0; jj < 4; jj++) {
            int n = q * 4 + jj;
            float s = b1h[n];
#pragma unroll 8
            for (int k = 0; k < HID; k++)
                s += h1T[(k >> 1) * MST + m * 2 + (k & 1)] * W1h[n * HID + k];
            pm += fmaxf(s, 0.0f) * W2h[n];
        }
#pragma unroll
        for (int off = 8; off > 0; off >>= 1)
            pm += __shfl_down_sync(0xffffffffu, pm, off, 16);
        if (q == 0) out[b0 + m] = pm + b2h[0];
    }
}

extern "C" void kernel_launch(void* const* d_in, const int* in_sizes, int n_in,
                              void* d_out, int out_size)
{
    const float* x    = (const float*)d_in[0];
    const float* Wih0 = (const float*)d_in[1];
    const float* Whh0 = (const float*)d_in[2];
    const float* bih0 = (const float*)d_in[3];
    const float* bhh0 = (const float*)d_in[4];
    const float* Wih1 = (const float*)d_in[5];
    const float* Whh1 = (const float*)d_in[6];
    const float* bih1 = (const float*)d_in[7];
    const float* bhh1 = (const float*)d_in[8];
    const float* W1   = (const float*)d_in[9];
    const float* b1   = (const float*)d_in[10];
    const float* W2   = (const float*)d_in[11];
    const float* b2   = (const float*)d_in[12];

    prep_kernel<<<64, 256>>>(Wih0, Whh0, bih0, bhh0, Wih1, Whh1, bih1, bhh1);

    size_t smem_bytes = (size_t)SMEMF * sizeof(float);   // 221184 B
    cudaFuncSetAttribute(lstm_fused,
                         cudaFuncAttributeMaxDynamicSharedMemorySize, (int)smem_bytes);
    lstm_fused<<<NCTA, NTHR, smem_bytes>>>(x, W1, b1, W2, b2, (float*)d_out);
}